// round 15
// baseline (speedup 1.0000x reference)
#include <cuda_runtime.h>
#include <cuda_fp16.h>
#include <cstdint>

#define N_NODES 50000
#define OUT_DIM 32

// ------------------------------------------------------------------ scratch
__device__ float g_sums[N_NODES * OUT_DIM];
__device__ float g_cnt[N_NODES];
__device__ float g_hx[N_NODES * 64];          // x @ W1[:32,:] + b1  (fp32 exact)
// Transposed, padded fp16 weight image: 45568 B = 2848 uint4
__device__ uint4 g_wimg[2848];

constexpr int TPB      = 384;   // 12 warps
constexpr int ROWS_PW  = 16;    // edges per warp
constexpr int TILE     = (TPB / 32) * ROWS_PW;   // 192 edges per CTA tile

// Weight image offsets (bytes). Wt[j][k] row-major fp16, stride = K*2+16.
constexpr int W1H = 0;        // W1e [64][32]  s=80   (5120 B)
constexpr int W2H = 5120;     // W2  [128][64] s=144  (18432 B)
constexpr int W3H = 23552;    // W3  [64][128] s=272  (17408 B)
constexpr int W4H = 40960;    // W4  [32][64]  s=144  (4608 B)
constexpr int WIMG_BYTES = 45568;

// smem layout (bytes)
constexpr int SM_BIAS    = WIMG_BYTES;        // b2@0(128) b3@128(64) b4@192(32)
constexpr int SM_STAGE   = SM_BIAS + 1152;
constexpr int STG_STRIDE = 96;                // floats/row: hx[64] | ea[32]
constexpr int STAGE_PW   = 16 * STG_STRIDE * 4;   // 6144 B per buffer
constexpr int SMEM_BYTES = SM_STAGE + (TPB / 32) * 2 * STAGE_PW;  // 194176

// ------------------------------------------------------------- small kernels
__global__ void init_kernel(const float* __restrict__ W1, const float* __restrict__ W2,
                            const float* __restrict__ W3, const float* __restrict__ W4,
                            int n_nodes) {
    int i = blockIdx.x * blockDim.x + threadIdx.x;
    if (i < n_nodes * OUT_DIM) g_sums[i] = 0.0f;
    if (i < n_nodes)           g_cnt[i]  = 0.0f;
    if (i < 20480) {
        float v; int hoff;
        if (i < 2048) {                   // W1e: input rows 32..63 -> Wt[64][32] s80
            int k = i >> 6, j = i & 63;
            v = W1[(k + 32) * 64 + j];
            hoff = W1H + j * 80 + k * 2;
        } else if (i < 10240) {           // W2 [64][128] -> Wt[128][64] s144
            int i2 = i - 2048; int k = i2 >> 7, j = i2 & 127;
            v = W2[k * 128 + j];
            hoff = W2H + j * 144 + k * 2;
        } else if (i < 18432) {           // W3 [128][64] -> Wt[64][128] s272
            int i2 = i - 10240; int k = i2 >> 6, j = i2 & 63;
            v = W3[k * 64 + j];
            hoff = W3H + j * 272 + k * 2;
        } else {                          // W4 [64][32] -> Wt[32][64] s144
            int i2 = i - 18432; int k = i2 >> 5, j = i2 & 31;
            v = W4[k * 32 + j];
            hoff = W4H + j * 144 + k * 2;
        }
        *(__half*)((char*)g_wimg + hoff) = __float2half(v);
    }
}

// h_x[n][j] = b1[j] + sum_{k<32} x[n][k] * W1[k][j]   (warp per node, fp32 exact)
__global__ void hx_kernel(const float* __restrict__ x, const float* __restrict__ W1,
                          const float* __restrict__ b1, int n_nodes) {
    int w = (blockIdx.x * blockDim.x + threadIdx.x) >> 5;
    int lane = threadIdx.x & 31;
    if (w >= n_nodes) return;
    float xv = x[(size_t)w * 32 + lane];
    float a0 = b1[lane], a1 = b1[lane + 32];
#pragma unroll
    for (int k = 0; k < 32; k++) {
        float xk = __shfl_sync(0xFFFFFFFFu, xv, k);
        a0 = fmaf(xk, W1[k * 64 + lane], a0);
        a1 = fmaf(xk, W1[k * 64 + lane + 32], a1);
    }
    g_hx[(size_t)w * 64 + lane]      = a0;
    g_hx[(size_t)w * 64 + lane + 32] = a1;
}

__global__ void finalize_kernel(float4* __restrict__ out, int n_nodes) {
    int i = blockIdx.x * blockDim.x + threadIdx.x;   // float4 index; 8 per node
    if (i < n_nodes * (OUT_DIM / 4)) {
        float c = fmaxf(g_cnt[i >> 3], 1.0f);
        float inv = 1.0f / c;
        float4 s = ((const float4*)g_sums)[i];
        out[i] = make_float4(s.x * inv, s.y * inv, s.z * inv, s.w * inv);
    }
}

// ---------------------------------------------------------------- primitives
__device__ __forceinline__ uint32_t smem_u32(const void* p) {
    uint32_t a;
    asm("{ .reg .u64 t; cvta.to.shared.u64 t, %1; cvt.u32.u64 %0, t; }" : "=r"(a) : "l"(p));
    return a;
}

__device__ __forceinline__ void ldsm4(uint32_t* r, uint32_t addr) {
    asm volatile("ldmatrix.sync.aligned.m8n8.x4.shared.b16 {%0,%1,%2,%3}, [%4];"
                 : "=r"(r[0]), "=r"(r[1]), "=r"(r[2]), "=r"(r[3]) : "r"(addr));
}

__device__ __forceinline__ void mma16816(float* d, const uint32_t* a,
                                         uint32_t b0, uint32_t b1) {
    asm volatile(
        "mma.sync.aligned.m16n8k16.row.col.f32.f16.f16.f32 "
        "{%0,%1,%2,%3}, {%4,%5,%6,%7}, {%8,%9}, {%0,%1,%2,%3};"
        : "+f"(d[0]), "+f"(d[1]), "+f"(d[2]), "+f"(d[3])
        : "r"(a[0]), "r"(a[1]), "r"(a[2]), "r"(a[3]), "r"(b0), "r"(b1));
}

__device__ __forceinline__ void mma16816h(uint32_t* d, const uint32_t* a,
                                          uint32_t b0, uint32_t b1) {
    asm volatile(
        "mma.sync.aligned.m16n8k16.row.col.f16.f16.f16.f16 "
        "{%0,%1}, {%2,%3,%4,%5}, {%6,%7}, {%0,%1};"
        : "+r"(d[0]), "+r"(d[1])
        : "r"(a[0]), "r"(a[1]), "r"(a[2]), "r"(a[3]), "r"(b0), "r"(b1));
}

__device__ __forceinline__ uint32_t pack_h2(float a, float b) {
    __half2 hb = __floats2half2_rn(a, b);
    return *reinterpret_cast<uint32_t*>(&hb);
}

__device__ __forceinline__ uint32_t relu2(uint32_t v) {
    __half2 h = *reinterpret_cast<__half2*>(&v);
    h = __hmax2(h, __float2half2_rn(0.0f));
    return *reinterpret_cast<uint32_t*>(&h);
}

__device__ __forceinline__ void red4(float* p, float a, float b, float c, float d) {
    asm volatile("red.global.add.v4.f32 [%0], {%1,%2,%3,%4};"
                 :: "l"(p), "f"(a), "f"(b), "f"(c), "f"(d) : "memory");
}

__device__ __forceinline__ void cp16(uint32_t saddr, const void* g) {
    asm volatile("cp.async.ca.shared.global [%0], [%1], 16;"
                 :: "r"(saddr), "l"(g) : "memory");
}
#define CP_COMMIT() asm volatile("cp.async.commit_group;" ::: "memory")
#define CP_WAIT1()  asm volatile("cp.async.wait_group 1;" ::: "memory")

// f32-acc quad GEMM core, no acc init (acc preloaded by caller)
template<int K16, int STRIDE>
__device__ __forceinline__ void quad_gemm_acc(float acc[16],
                                              const uint32_t (*Ah)[4],
                                              uint32_t bH, int jb0, int lane) {
    const uint32_t base = bH + (uint32_t)jb0 * 8 * STRIDE +
                          (lane & 7) * STRIDE + (lane >> 3) * 16;
#pragma unroll
    for (int c = 0; c < K16; c += 2) {
        uint32_t h[4][4];
#pragma unroll
        for (int i = 0; i < 4; i++) ldsm4(h[i], base + i * 8 * STRIDE + c * 32);
#pragma unroll
        for (int i = 0; i < 4; i++) mma16816(acc + 4 * i, Ah[c], h[i][0], h[i][1]);
#pragma unroll
        for (int i = 0; i < 4; i++) mma16816(acc + 4 * i, Ah[c + 1], h[i][2], h[i][3]);
    }
}

// f32-acc quad GEMM with bias preload
template<int K16, int STRIDE>
__device__ __forceinline__ void quad_gemm(float acc[16],
                                          const uint32_t (*Ah)[4],
                                          uint32_t bH, int jb0, int lane,
                                          const float* bias_base) {
#pragma unroll
    for (int i = 0; i < 4; i++) {
        float2 bb = *(const float2*)(bias_base + (jb0 + i) * 8 + (lane & 3) * 2);
        acc[4 * i + 0] = bb.x; acc[4 * i + 1] = bb.y;
        acc[4 * i + 2] = bb.x; acc[4 * i + 3] = bb.y;
    }
    quad_gemm_acc<K16, STRIDE>(acc, Ah, bH, jb0, lane);
}

// f16-acc quad GEMM with bias preload
template<int K16, int STRIDE>
__device__ __forceinline__ void quad_gemm_h(uint32_t acc[8],
                                            const uint32_t (*Ah)[4],
                                            uint32_t bH, int jb0, int lane,
                                            const float* bias_base) {
#pragma unroll
    for (int i = 0; i < 4; i++) {
        float2 bb = *(const float2*)(bias_base + (jb0 + i) * 8 + (lane & 3) * 2);
        uint32_t pb = pack_h2(bb.x, bb.y);
        acc[2 * i + 0] = pb; acc[2 * i + 1] = pb;
    }
    const uint32_t base = bH + (uint32_t)jb0 * 8 * STRIDE +
                          (lane & 7) * STRIDE + (lane >> 3) * 16;
#pragma unroll
    for (int c = 0; c < K16; c += 2) {
        uint32_t h[4][4];
#pragma unroll
        for (int i = 0; i < 4; i++) ldsm4(h[i], base + i * 8 * STRIDE + c * 32);
#pragma unroll
        for (int i = 0; i < 4; i++) mma16816h(acc + 2 * i, Ah[c], h[i][0], h[i][1]);
#pragma unroll
        for (int i = 0; i < 4; i++) mma16816h(acc + 2 * i, Ah[c + 1], h[i][2], h[i][3]);
    }
}

__device__ __forceinline__ void epi_frag(const float acc[8], uint32_t* nh) {
    nh[0] = pack_h2(fmaxf(acc[0], 0.f), fmaxf(acc[1], 0.f));
    nh[1] = pack_h2(fmaxf(acc[2], 0.f), fmaxf(acc[3], 0.f));
    nh[2] = pack_h2(fmaxf(acc[4], 0.f), fmaxf(acc[5], 0.f));
    nh[3] = pack_h2(fmaxf(acc[6], 0.f), fmaxf(acc[7], 0.f));
}

// --------------------------------------------------------------- main kernel
__global__ __launch_bounds__(TPB, 1)
void gnn_mma_kernel(const int* __restrict__ ei,
                    const float* __restrict__ ea,
                    const float* __restrict__ b2, const float* __restrict__ b3,
                    const float* __restrict__ b4,
                    int E, int n_nodes, int ntiles) {
    extern __shared__ char smem[];
    const uint32_t sb = smem_u32(smem);
    const int t = threadIdx.x;
    const int wid = t >> 5;
    const int lane = t & 31;

    // stage weights + biases into smem
    {
        uint4* dst = (uint4*)smem;
        for (int i = t; i < 2848; i += TPB) dst[i] = g_wimg[i];
        float* sB = (float*)(smem + SM_BIAS);
        if (t < 128) sB[t] = b2[t];
        if (t < 64)  sB[128 + t] = b3[t];
        if (t < 32)  sB[192 + t] = b4[t];
    }
    __syncthreads();

    const float* sBias = (const float*)(smem + SM_BIAS);
    const uint32_t stg_base = sb + SM_STAGE + wid * (2 * STAGE_PW);

    const int rA = lane >> 2, rB = rA + 8;

    // Issue gather for a tile into staging buffer (cp.async), return dst indices.
    auto issue_gather = [&](int tile, uint32_t stg_u32) -> int {
        const int ebase = tile * TILE + wid * ROWS_PW;
        int dstv = 0;
        if (lane < ROWS_PW) {
            int e = ebase + lane;
            if (e < E) {
                dstv = min(max(ei[(size_t)E + e], 0), n_nodes - 1);
                atomicAdd(&g_cnt[dstv], 1.0f);
            }
        }
        __syncwarp();
#pragma unroll
        for (int p = 0; p < 12; p++) {
            int flat = p * 32 + lane;
            int row = flat / 24, q = flat % 24;
            int e = min(ebase + row, E - 1);      // clamped: invalid rows never scatter
            int d = __shfl_sync(0xFFFFFFFFu, dstv, row);
            const float* g = (q < 16) ? (g_hx + (size_t)d * 64 + q * 4)
                                      : (ea + (size_t)e * 32 + (q - 16) * 4);
            cp16(stg_u32 + row * (STG_STRIDE * 4) + q * 16, g);
        }
        return dstv;
    };

    int tile = blockIdx.x;
    int buf = 0;
    int dstv_cur = 0;
    if (tile < ntiles) dstv_cur = issue_gather(tile, stg_base);
    CP_COMMIT();

    for (; tile < ntiles; tile += gridDim.x) {
        const int next = tile + gridDim.x;
        int dstv_next = 0;
        if (next < ntiles) dstv_next = issue_gather(next, stg_base + (buf ^ 1) * STAGE_PW);
        CP_COMMIT();
        CP_WAIT1();
        __syncwarp();

        const float* stg = (const float*)(smem + SM_STAGE +
                                          wid * (2 * STAGE_PW) + buf * STAGE_PW);
        const int ebase = tile * TILE + wid * ROWS_PW;
        const bool validA = ebase + rA < E, validB = ebase + rB < E;
        const int dstA = __shfl_sync(0xFFFFFFFFu, dstv_cur, rA);
        const int dstB = __shfl_sync(0xFFFFFFFFu, dstv_cur, rB);

        // ---- build A1 fragments from ea (K=32), fp16 ----
        uint32_t A1h[2][4];
#pragma unroll
        for (int c = 0; c < 2; c++) {
            int colA = 64 + 16 * c + (lane & 3) * 2;
            float2 f0 = *(const float2*)(stg + rA * STG_STRIDE + colA);
            float2 f1 = *(const float2*)(stg + rB * STG_STRIDE + colA);
            float2 f2 = *(const float2*)(stg + rA * STG_STRIDE + colA + 8);
            float2 f3 = *(const float2*)(stg + rB * STG_STRIDE + colA + 8);
            A1h[c][0] = pack_h2(f0.x, f0.y);
            A1h[c][1] = pack_h2(f1.x, f1.y);
            A1h[c][2] = pack_h2(f2.x, f2.y);
            A1h[c][3] = pack_h2(f3.x, f3.y);
        }

        float acc[16];

        // ---- L1: acc preloaded with h_x[dst]+b1 (f32), + ea @ W1e (K16=2) ----
        uint32_t A2h[4][4];
#pragma unroll
        for (int q = 0; q < 2; q++) {
#pragma unroll
            for (int i = 0; i < 4; i++) {
                int col = (4 * q + i) * 8 + (lane & 3) * 2;
                float2 uA = *(const float2*)(stg + rA * STG_STRIDE + col);
                float2 uB = *(const float2*)(stg + rB * STG_STRIDE + col);
                acc[4 * i + 0] = uA.x; acc[4 * i + 1] = uA.y;
                acc[4 * i + 2] = uB.x; acc[4 * i + 3] = uB.y;
            }
            quad_gemm_acc<2, 80>(acc, A1h, sb + W1H, 4 * q, lane);
            epi_frag(acc,     A2h[2 * q]);
            epi_frag(acc + 8, A2h[2 * q + 1]);
        }

        // ---- L2: 64 -> 128 (4 quads, f16 acc) ----
        uint32_t A3h[8][4];
#pragma unroll
        for (int q = 0; q < 4; q++) {
            uint32_t acch[8];
            quad_gemm_h<4, 144>(acch, A2h, sb + W2H, 4 * q, lane, sBias);
            A3h[2 * q][0]     = relu2(acch[0]);
            A3h[2 * q][1]     = relu2(acch[1]);
            A3h[2 * q][2]     = relu2(acch[2]);
            A3h[2 * q][3]     = relu2(acch[3]);
            A3h[2 * q + 1][0] = relu2(acch[4]);
            A3h[2 * q + 1][1] = relu2(acch[5]);
            A3h[2 * q + 1][2] = relu2(acch[6]);
            A3h[2 * q + 1][3] = relu2(acch[7]);
        }

        // ---- L3: 128 -> 64 (2 quads, K16=8, f16 acc) ----
        uint32_t A4h[4][4];
#pragma unroll
        for (int q = 0; q < 2; q++) {
            uint32_t acch[8];
            quad_gemm_h<8, 272>(acch, A3h, sb + W3H, 4 * q, lane, sBias + 128);
            A4h[2 * q][0]     = relu2(acch[0]);
            A4h[2 * q][1]     = relu2(acch[1]);
            A4h[2 * q][2]     = relu2(acch[2]);
            A4h[2 * q][3]     = relu2(acch[3]);
            A4h[2 * q + 1][0] = relu2(acch[4]);
            A4h[2 * q + 1][1] = relu2(acch[5]);
            A4h[2 * q + 1][2] = relu2(acch[6]);
            A4h[2 * q + 1][3] = relu2(acch[7]);
        }

        // ---- L4: 64 -> 32 (1 quad, f32 acc) + float4 red scatter ----
        quad_gemm<4, 144>(acc, A4h, sb + W4H, 0, lane, sBias + 192);
#pragma unroll
        for (int b = 0; b < 4; b++) {
            float a0 = fmaxf(acc[4 * b + 0], 0.f);
            float a1 = fmaxf(acc[4 * b + 1], 0.f);
            float a2 = fmaxf(acc[4 * b + 2], 0.f);
            float a3 = fmaxf(acc[4 * b + 3], 0.f);
            float p0 = __shfl_xor_sync(0xFFFFFFFFu, a0, 1);
            float p1 = __shfl_xor_sync(0xFFFFFFFFu, a1, 1);
            float p2 = __shfl_xor_sync(0xFFFFFFFFu, a2, 1);
            float p3 = __shfl_xor_sync(0xFFFFFFFFu, a3, 1);
            if ((lane & 1) == 0) {
                int col = 8 * b + (lane & 3) * 2;
                if (validA) red4(&g_sums[(size_t)dstA * 32 + col], a0, a1, p0, p1);
                if (validB) red4(&g_sums[(size_t)dstB * 32 + col], a2, a3, p2, p3);
            }
        }

        dstv_cur = dstv_next;
        buf ^= 1;
    }
}

// ------------------------------------------------------------------- launch
extern "C" void kernel_launch(void* const* d_in, const int* in_sizes, int n_in,
                              void* d_out, int out_size) {
    const float* x  = (const float*)d_in[0];
    const int*   ei = (const int*)d_in[1];
    const float* ea = (const float*)d_in[2];
    const float* W1 = (const float*)d_in[3];  const float* b1 = (const float*)d_in[4];
    const float* W2 = (const float*)d_in[5];  const float* b2 = (const float*)d_in[6];
    const float* W3 = (const float*)d_in[7];  const float* b3 = (const float*)d_in[8];
    const float* W4 = (const float*)d_in[9];  const float* b4 = (const float*)d_in[10];

    const int E       = in_sizes[2] / 32;
    const int n_nodes = in_sizes[0] / 32;
    const int ntiles  = (E + TILE - 1) / TILE;

    int dev = 0, sms = 148;
    cudaGetDevice(&dev);
    cudaDeviceGetAttribute(&sms, cudaDevAttrMultiProcessorCount, dev);
    cudaFuncSetAttribute(gnn_mma_kernel,
                         cudaFuncAttributeMaxDynamicSharedMemorySize, SMEM_BYTES);

    const int zn = n_nodes * OUT_DIM;
    init_kernel<<<(zn + 255) / 256, 256>>>(W1, W2, W3, W4, n_nodes);
    hx_kernel<<<(n_nodes * 32 + 255) / 256, 256>>>(x, W1, b1, n_nodes);

    const int grid = (sms < ntiles) ? sms : ntiles;
    gnn_mma_kernel<<<grid, TPB, SMEM_BYTES>>>(ei, ea, b2, b3, b4,
                                              E, n_nodes, ntiles);

    finalize_kernel<<<(zn / 4 + 255) / 256, 256>>>((float4*)d_out, n_nodes);
}

// round 16
// speedup vs baseline: 1.3457x; 1.3457x over previous
#include <cuda_runtime.h>
#include <cuda_fp16.h>
#include <cstdint>

#define N_NODES 50000
#define OUT_DIM 32

// ------------------------------------------------------------------ scratch
__device__ float g_sums[N_NODES * OUT_DIM];
__device__ float g_cnt[N_NODES];
// Transposed, padded fp16 weight image: 49664 B = 3104 uint4
__device__ uint4 g_wimg[3104];

constexpr int TPB      = 512;   // 16 warps
constexpr int ROWS_PW  = 16;    // edges per warp
constexpr int TILE     = (TPB / 32) * ROWS_PW;   // 256 edges per CTA tile

// Weight image offsets (bytes). Wt[j][k] row-major fp16, stride = K*2+16.
constexpr int W1H = 0;        // [64][64]   s=144  (9216 B)
constexpr int W2H = 9216;     // [128][64]  s=144  (18432 B)
constexpr int W3H = 27648;    // [64][128]  s=272  (17408 B)
constexpr int W4H = 45056;    // [32][64]   s=144  (4608 B)
constexpr int WIMG_BYTES = 49664;

// smem layout (bytes)
constexpr int SM_BIAS  = WIMG_BYTES;            // 288 floats
constexpr int SM_STAGE = SM_BIAS + 1152;
constexpr int STAGE_PW = 16 * 72 * 4;           // 4608 B per buffer
constexpr int SMEM_BYTES = SM_STAGE + (TPB / 32) * 2 * STAGE_PW;  // 198272

// ------------------------------------------------------------- small kernels
// zero scratch (vectorized) + build fp16 weight image (merged)
__global__ void init_kernel(const float* __restrict__ W1, const float* __restrict__ W2,
                            const float* __restrict__ W3, const float* __restrict__ W4,
                            int n_nodes) {
    int i = blockIdx.x * blockDim.x + threadIdx.x;
    const float4 z4 = make_float4(0.f, 0.f, 0.f, 0.f);
    if (i < n_nodes * (OUT_DIM / 4)) ((float4*)g_sums)[i] = z4;   // 400K float4
    if (i < n_nodes) g_cnt[i] = 0.0f;
    if (i < 22528) {
        float v; int hoff;
        if (i < 4096) {                   // W1 [64][64] -> Wt[64][64] s144
            int k = i >> 6, j = i & 63;
            v = W1[k * 64 + j];
            hoff = W1H + j * 144 + k * 2;
        } else if (i < 12288) {           // W2 [64][128] -> Wt[128][64] s144
            int i2 = i - 4096; int k = i2 >> 7, j = i2 & 127;
            v = W2[k * 128 + j];
            hoff = W2H + j * 144 + k * 2;
        } else if (i < 20480) {           // W3 [128][64] -> Wt[64][128] s272
            int i2 = i - 12288; int k = i2 >> 6, j = i2 & 63;
            v = W3[k * 64 + j];
            hoff = W3H + j * 272 + k * 2;
        } else {                          // W4 [64][32] -> Wt[32][64] s144
            int i2 = i - 20480; int k = i2 >> 5, j = i2 & 31;
            v = W4[k * 32 + j];
            hoff = W4H + j * 144 + k * 2;
        }
        *(__half*)((char*)g_wimg + hoff) = __float2half(v);
    }
}

__global__ void finalize_kernel(float4* __restrict__ out, int n_nodes) {
    int i = blockIdx.x * blockDim.x + threadIdx.x;   // float4 index; 8 per node
    if (i < n_nodes * (OUT_DIM / 4)) {
        float c = fmaxf(g_cnt[i >> 3], 1.0f);
        float inv = 1.0f / c;
        float4 s = ((const float4*)g_sums)[i];
        out[i] = make_float4(s.x * inv, s.y * inv, s.z * inv, s.w * inv);
    }
}

// ---------------------------------------------------------------- primitives
__device__ __forceinline__ uint32_t smem_u32(const void* p) {
    uint32_t a;
    asm("{ .reg .u64 t; cvta.to.shared.u64 t, %1; cvt.u32.u64 %0, t; }" : "=r"(a) : "l"(p));
    return a;
}

__device__ __forceinline__ void ldsm4(uint32_t* r, uint32_t addr) {
    asm volatile("ldmatrix.sync.aligned.m8n8.x4.shared.b16 {%0,%1,%2,%3}, [%4];"
                 : "=r"(r[0]), "=r"(r[1]), "=r"(r[2]), "=r"(r[3]) : "r"(addr));
}

__device__ __forceinline__ void mma16816(float* d, const uint32_t* a,
                                         uint32_t b0, uint32_t b1) {
    asm volatile(
        "mma.sync.aligned.m16n8k16.row.col.f32.f16.f16.f32 "
        "{%0,%1,%2,%3}, {%4,%5,%6,%7}, {%8,%9}, {%0,%1,%2,%3};"
        : "+f"(d[0]), "+f"(d[1]), "+f"(d[2]), "+f"(d[3])
        : "r"(a[0]), "r"(a[1]), "r"(a[2]), "r"(a[3]), "r"(b0), "r"(b1));
}

// fp16-accumulate variant: D/C are 2 packed-half2 regs (same layout as next A frag)
__device__ __forceinline__ void mma16816h(uint32_t* d, const uint32_t* a,
                                          uint32_t b0, uint32_t b1) {
    asm volatile(
        "mma.sync.aligned.m16n8k16.row.col.f16.f16.f16.f16 "
        "{%0,%1}, {%2,%3,%4,%5}, {%6,%7}, {%0,%1};"
        : "+r"(d[0]), "+r"(d[1])
        : "r"(a[0]), "r"(a[1]), "r"(a[2]), "r"(a[3]), "r"(b0), "r"(b1));
}

__device__ __forceinline__ uint32_t pack_h2(float a, float b) {
    __half2 hb = __floats2half2_rn(a, b);
    return *reinterpret_cast<uint32_t*>(&hb);
}

__device__ __forceinline__ uint32_t relu2(uint32_t v) {
    __half2 h = *reinterpret_cast<__half2*>(&v);
    h = __hmax2(h, __float2half2_rn(0.0f));
    return *reinterpret_cast<uint32_t*>(&h);
}

__device__ __forceinline__ void red4(float* p, float a, float b, float c, float d) {
    asm volatile("red.global.add.v4.f32 [%0], {%1,%2,%3,%4};"
                 :: "l"(p), "f"(a), "f"(b), "f"(c), "f"(d) : "memory");
}

__device__ __forceinline__ void cp16(uint32_t saddr, const void* g) {
    asm volatile("cp.async.ca.shared.global [%0], [%1], 16;"
                 :: "r"(saddr), "l"(g) : "memory");
}
#define CP_COMMIT() asm volatile("cp.async.commit_group;" ::: "memory")
#define CP_WAIT1()  asm volatile("cp.async.wait_group 1;" ::: "memory")

// f32-acc quad GEMM (bias preloaded into accumulators)
template<int K16, int STRIDE>
__device__ __forceinline__ void quad_gemm(float acc[16],
                                          const uint32_t (*Ah)[4],
                                          uint32_t bH, int jb0, int lane,
                                          const float* bias_base) {
#pragma unroll
    for (int i = 0; i < 4; i++) {
        float2 bb = *(const float2*)(bias_base + (jb0 + i) * 8 + (lane & 3) * 2);
        acc[4 * i + 0] = bb.x; acc[4 * i + 1] = bb.y;
        acc[4 * i + 2] = bb.x; acc[4 * i + 3] = bb.y;
    }
    const uint32_t base = bH + (uint32_t)jb0 * 8 * STRIDE +
                          (lane & 7) * STRIDE + (lane >> 3) * 16;
#pragma unroll
    for (int c = 0; c < K16; c += 2) {
        uint32_t h[4][4];
#pragma unroll
        for (int i = 0; i < 4; i++) ldsm4(h[i], base + i * 8 * STRIDE + c * 32);
#pragma unroll
        for (int i = 0; i < 4; i++) mma16816(acc + 4 * i, Ah[c], h[i][0], h[i][1]);
#pragma unroll
        for (int i = 0; i < 4; i++) mma16816(acc + 4 * i, Ah[c + 1], h[i][2], h[i][3]);
    }
}

// f16-acc quad GEMM: acc[2i..2i+1] = packed-half2 D of n8 block jb0+i.
template<int K16, int STRIDE>
__device__ __forceinline__ void quad_gemm_h(uint32_t acc[8],
                                            const uint32_t (*Ah)[4],
                                            uint32_t bH, int jb0, int lane,
                                            const float* bias_base) {
#pragma unroll
    for (int i = 0; i < 4; i++) {
        float2 bb = *(const float2*)(bias_base + (jb0 + i) * 8 + (lane & 3) * 2);
        uint32_t pb = pack_h2(bb.x, bb.y);
        acc[2 * i + 0] = pb; acc[2 * i + 1] = pb;
    }
    const uint32_t base = bH + (uint32_t)jb0 * 8 * STRIDE +
                          (lane & 7) * STRIDE + (lane >> 3) * 16;
#pragma unroll
    for (int c = 0; c < K16; c += 2) {
        uint32_t h[4][4];
#pragma unroll
        for (int i = 0; i < 4; i++) ldsm4(h[i], base + i * 8 * STRIDE + c * 32);
#pragma unroll
        for (int i = 0; i < 4; i++) mma16816h(acc + 2 * i, Ah[c], h[i][0], h[i][1]);
#pragma unroll
        for (int i = 0; i < 4; i++) mma16816h(acc + 2 * i, Ah[c + 1], h[i][2], h[i][3]);
    }
}

__device__ __forceinline__ void epi_frag(const float acc[8], uint32_t* nh) {
    nh[0] = pack_h2(fmaxf(acc[0], 0.f), fmaxf(acc[1], 0.f));
    nh[1] = pack_h2(fmaxf(acc[2], 0.f), fmaxf(acc[3], 0.f));
    nh[2] = pack_h2(fmaxf(acc[4], 0.f), fmaxf(acc[5], 0.f));
    nh[3] = pack_h2(fmaxf(acc[6], 0.f), fmaxf(acc[7], 0.f));
}

// --------------------------------------------------------------- main kernel
__global__ __launch_bounds__(TPB, 1)
void gnn_mma_kernel(const float* __restrict__ x,
                    const int* __restrict__ ei,
                    const float* __restrict__ ea,
                    const float* __restrict__ b1, const float* __restrict__ b2,
                    const float* __restrict__ b3, const float* __restrict__ b4,
                    int E, int n_nodes, int ntiles) {
    extern __shared__ char smem[];
    const uint32_t sb = smem_u32(smem);
    const int t = threadIdx.x;
    const int wid = t >> 5;
    const int lane = t & 31;

    // stage weights + biases into smem
    {
        uint4* dst = (uint4*)smem;
        for (int i = t; i < 3104; i += TPB) dst[i] = g_wimg[i];
        float* sB = (float*)(smem + SM_BIAS);
        if (t < 64)  sB[t] = b1[t];
        if (t < 128) sB[64 + t] = b2[t];
        if (t < 64)  sB[192 + t] = b3[t];
        if (t < 32)  sB[256 + t] = b4[t];
    }
    __syncthreads();

    const float* sBias = (const float*)(smem + SM_BIAS);
    const uint32_t stg_base = sb + SM_STAGE + wid * (2 * STAGE_PW);

    const int rA = lane >> 2, rB = rA + 8;

    // Issue gather for a tile into staging buffer (cp.async), return dst indices.
    auto issue_gather = [&](int tile, uint32_t stg_u32) -> int {
        const int ebase = tile * TILE + wid * ROWS_PW;
        int dstv = 0;
        if (lane < ROWS_PW) {
            int e = ebase + lane;
            if (e < E) {
                dstv = min(max(ei[(size_t)E + e], 0), n_nodes - 1);
                atomicAdd(&g_cnt[dstv], 1.0f);
            }
        }
        __syncwarp();
#pragma unroll
        for (int p = 0; p < 8; p++) {
            int flat = p * 32 + lane;
            int row = flat >> 4, q = flat & 15;
            int e = min(ebase + row, E - 1);      // clamped: invalid rows never scatter
            int d = __shfl_sync(0xFFFFFFFFu, dstv, row);
            const float* g = (q < 8) ? (x + (size_t)d * 32 + q * 4)
                                     : (ea + (size_t)e * 32 + (q - 8) * 4);
            cp16(stg_u32 + row * 288 + q * 16, g);
        }
        return dstv;
    };

    int tile = blockIdx.x;
    int buf = 0;
    int dstv_cur = 0;
    if (tile < ntiles) dstv_cur = issue_gather(tile, stg_base);
    CP_COMMIT();

    for (; tile < ntiles; tile += gridDim.x) {
        const int next = tile + gridDim.x;
        int dstv_next = 0;
        if (next < ntiles) dstv_next = issue_gather(next, stg_base + (buf ^ 1) * STAGE_PW);
        CP_COMMIT();
        CP_WAIT1();
        __syncwarp();

        const float* stg = (const float*)(smem + SM_STAGE +
                                          wid * (2 * STAGE_PW) + buf * STAGE_PW);
        const int ebase = tile * TILE + wid * ROWS_PW;
        const bool validA = ebase + rA < E, validB = ebase + rB < E;
        const int dstA = __shfl_sync(0xFFFFFFFFu, dstv_cur, rA);
        const int dstB = __shfl_sync(0xFFFFFFFFu, dstv_cur, rB);

        // ---- build A1 fragments (K=64), fp16 ----
        uint32_t A1h[4][4];
#pragma unroll
        for (int c = 0; c < 4; c++) {
            int colA = 16 * c + (lane & 3) * 2;
            float2 f0 = *(const float2*)(stg + rA * 72 + colA);
            float2 f1 = *(const float2*)(stg + rB * 72 + colA);
            float2 f2 = *(const float2*)(stg + rA * 72 + colA + 8);
            float2 f3 = *(const float2*)(stg + rB * 72 + colA + 8);
            A1h[c][0] = pack_h2(f0.x, f0.y);
            A1h[c][1] = pack_h2(f1.x, f1.y);
            A1h[c][2] = pack_h2(f2.x, f2.y);
            A1h[c][3] = pack_h2(f3.x, f3.y);
        }

        float acc[16];

        // ---- L1: 64 -> 64 (2 quads, f32 acc) ----
        uint32_t A2h[4][4];
#pragma unroll
        for (int q = 0; q < 2; q++) {
            quad_gemm<4, 144>(acc, A1h, sb + W1H, 4 * q, lane, sBias);
            epi_frag(acc,     A2h[2 * q]);
            epi_frag(acc + 8, A2h[2 * q + 1]);
        }

        // ---- L2: 64 -> 128 (4 quads, f16 acc; D frag == next A frag) ----
        uint32_t A3h[8][4];
#pragma unroll
        for (int q = 0; q < 4; q++) {
            uint32_t acch[8];
            quad_gemm_h<4, 144>(acch, A2h, sb + W2H, 4 * q, lane, sBias + 64);
            A3h[2 * q][0]     = relu2(acch[0]);
            A3h[2 * q][1]     = relu2(acch[1]);
            A3h[2 * q][2]     = relu2(acch[2]);
            A3h[2 * q][3]     = relu2(acch[3]);
            A3h[2 * q + 1][0] = relu2(acch[4]);
            A3h[2 * q + 1][1] = relu2(acch[5]);
            A3h[2 * q + 1][2] = relu2(acch[6]);
            A3h[2 * q + 1][3] = relu2(acch[7]);
        }

        // ---- L3: 128 -> 64 (2 quads, K16=8, f16 acc) ----
        uint32_t A4h[4][4];
#pragma unroll
        for (int q = 0; q < 2; q++) {
            uint32_t acch[8];
            quad_gemm_h<8, 272>(acch, A3h, sb + W3H, 4 * q, lane, sBias + 192);
            A4h[2 * q][0]     = relu2(acch[0]);
            A4h[2 * q][1]     = relu2(acch[1]);
            A4h[2 * q][2]     = relu2(acch[2]);
            A4h[2 * q][3]     = relu2(acch[3]);
            A4h[2 * q + 1][0] = relu2(acch[4]);
            A4h[2 * q + 1][1] = relu2(acch[5]);
            A4h[2 * q + 1][2] = relu2(acch[6]);
            A4h[2 * q + 1][3] = relu2(acch[7]);
        }

        // ---- L4: 64 -> 32 (1 quad, f32 acc) + float4 red scatter ----
        quad_gemm<4, 144>(acc, A4h, sb + W4H, 0, lane, sBias + 256);
#pragma unroll
        for (int b = 0; b < 4; b++) {
            float a0 = fmaxf(acc[4 * b + 0], 0.f);
            float a1 = fmaxf(acc[4 * b + 1], 0.f);
            float a2 = fmaxf(acc[4 * b + 2], 0.f);
            float a3 = fmaxf(acc[4 * b + 3], 0.f);
            float p0 = __shfl_xor_sync(0xFFFFFFFFu, a0, 1);
            float p1 = __shfl_xor_sync(0xFFFFFFFFu, a1, 1);
            float p2 = __shfl_xor_sync(0xFFFFFFFFu, a2, 1);
            float p3 = __shfl_xor_sync(0xFFFFFFFFu, a3, 1);
            if ((lane & 1) == 0) {
                int col = 8 * b + (lane & 3) * 2;
                if (validA) red4(&g_sums[(size_t)dstA * 32 + col], a0, a1, p0, p1);
                if (validB) red4(&g_sums[(size_t)dstB * 32 + col], a2, a3, p2, p3);
            }
        }

        dstv_cur = dstv_next;
        buf ^= 1;
    }
}

// ------------------------------------------------------------------- launch
extern "C" void kernel_launch(void* const* d_in, const int* in_sizes, int n_in,
                              void* d_out, int out_size) {
    const float* x  = (const float*)d_in[0];
    const int*   ei = (const int*)d_in[1];
    const float* ea = (const float*)d_in[2];
    const float* W1 = (const float*)d_in[3];  const float* b1 = (const float*)d_in[4];
    const float* W2 = (const float*)d_in[5];  const float* b2 = (const float*)d_in[6];
    const float* W3 = (const float*)d_in[7];  const float* b3 = (const float*)d_in[8];
    const float* W4 = (const float*)d_in[9];  const float* b4 = (const float*)d_in[10];

    const int E       = in_sizes[2] / 32;
    const int n_nodes = in_sizes[0] / 32;
    const int ntiles  = (E + TILE - 1) / TILE;

    int dev = 0, sms = 148;
    cudaGetDevice(&dev);
    cudaDeviceGetAttribute(&sms, cudaDevAttrMultiProcessorCount, dev);
    cudaFuncSetAttribute(gnn_mma_kernel,
                         cudaFuncAttributeMaxDynamicSharedMemorySize, SMEM_BYTES);

    const int zn = n_nodes * OUT_DIM;
    init_kernel<<<(zn / 4 + 255) / 256, 256>>>(W1, W2, W3, W4, n_nodes);

    const int grid = (sms < ntiles) ? sms : ntiles;
    gnn_mma_kernel<<<grid, TPB, SMEM_BYTES>>>(x, ei, ea, b1, b2, b3, b4,
                                              E, n_nodes, ntiles);

    finalize_kernel<<<(zn / 4 + 255) / 256, 256>>>((float4*)d_out, n_nodes);
}